// round 3
// baseline (speedup 1.0000x reference)
#include <cuda_runtime.h>
#include <math.h>

// B=256, T=64, D=16, S=64, H=128, O=8
#define NTHR 256

// Pre-transposed Wf3: g_Wf3T[k*1024+n] = Wf3[n*128+k]  (512 KB, L2-resident)
__device__ __align__(16) float g_Wf3T[128 * 1024];

__constant__ float cC[6]  = {0.0f, 0.161f, 0.327f, 0.9f, 0.9800255409045097f, 1.0f};
__constant__ float cBw[6] = {0.09646076681806523f, 0.01f, 0.4798896504144996f,
                             1.379008574103742f, -3.290069515436081f, 2.324710524099774f};
__constant__ float cA[6][5] = {
    {0.f, 0.f, 0.f, 0.f, 0.f},
    {0.161f, 0.f, 0.f, 0.f, 0.f},
    {-0.008480655492356989f, 0.335480655492357f, 0.f, 0.f, 0.f},
    {2.8971530571054935f, -6.359448489975075f, 4.3622954328695815f, 0.f, 0.f},
    {5.325864828439257f, -11.748883564062828f, 7.4955393428898365f, -0.09249506636175525f, 0.f},
    {5.86145544294642f, -12.92096931784711f, 8.159367898576159f, -0.071584973281401f,
     -0.028269050394068383f}};

struct Smem {
    unsigned long long yjd[4][64];    // duplicated-pair (v,v) of yj
    unsigned long long h1d[4][128];   // duplicated-pair h1
    unsigned long long h2d[4][128];   // duplicated-pair h2
    float Wf1T[64 * 128];             // [s][i]
    float Wf2T[128 * 128];            // [k][i]
    float bf1v[128];
    float bf2v[128];
    float bf3v[1024];
    float y[4][64];
    float ks[6][4][64];
    float dx[4][16];
    float cbv[4][16];
    float ccv[4][16];
    float cdv[4][16];
};

__device__ __forceinline__ unsigned long long fma2(unsigned long long a,
                                                   unsigned long long b,
                                                   unsigned long long c) {
    unsigned long long d;
    asm("fma.rn.f32x2 %0, %1, %2, %3;" : "=l"(d) : "l"(a), "l"(b), "l"(c));
    return d;
}
__device__ __forceinline__ unsigned long long dup2(float v) {
    unsigned long long r;
    asm("mov.b64 %0, {%1, %1};" : "=l"(r) : "f"(v));
    return r;
}
__device__ __forceinline__ float2 u2f(unsigned long long v) {
    float2 r;
    asm("mov.b64 {%0, %1}, %2;" : "=f"(r.x), "=f"(r.y) : "l"(v));
    return r;
}
__device__ __forceinline__ void ldg128(const float* p, unsigned long long& a,
                                       unsigned long long& b) {
    asm("ld.global.nc.v2.u64 {%0, %1}, [%2];" : "=l"(a), "=l"(b) : "l"(p));
}
// exact identity with jax.nn.softplus = log1p(exp(x))
__device__ __forceinline__ float softplus_f(float x) {
    return fmaxf(x, 0.0f) + log1pf(__expf(-fabsf(x)));
}
// tanh(x) = 1 - 2/(exp(2x)+1)
__device__ __forceinline__ float tanh_fast(float x) {
    float e = __expf(2.0f * x);
    return 1.0f - 2.0f / (e + 1.0f);
}

__global__ void __launch_bounds__(NTHR, 1) prep_kernel(const float* __restrict__ Wf3) {
    int idx = blockIdx.x * NTHR + threadIdx.x;  // 512 blocks
    int k = idx >> 10;
    int n = idx & 1023;
    g_Wf3T[idx] = Wf3[n * 128 + k];
}

__global__ void __launch_bounds__(NTHR, 1) cde_kernel(
    const float* __restrict__ ts,
    const float* __restrict__ coeff_d, const float* __restrict__ coeff_c,
    const float* __restrict__ coeff_b, const float* __restrict__ coeff_a,
    const float* __restrict__ Wi1, const float* __restrict__ bi1,
    const float* __restrict__ Wi2, const float* __restrict__ bi2,
    const float* __restrict__ Wf1, const float* __restrict__ bf1,
    const float* __restrict__ Wf2, const float* __restrict__ bf2,
    const float* __restrict__ bf3,
    const float* __restrict__ Wr, const float* __restrict__ br,
    float* __restrict__ out)
{
    extern __shared__ char smraw[];
    Smem& sm = *reinterpret_cast<Smem*>(smraw);
    const int tid = threadIdx.x;
    const int b0 = blockIdx.x * 4;  // 4 batch rows per CTA

    // ---- one-time init ----
    for (int idx = tid; idx < 64 * 128; idx += NTHR) {
        int s = idx >> 7, i = idx & 127;
        sm.Wf1T[idx] = Wf1[i * 64 + s];
    }
    for (int idx = tid; idx < 128 * 128; idx += NTHR) {
        int k = idx >> 7, i = idx & 127;
        sm.Wf2T[idx] = Wf2[i * 128 + k];
    }
    if (tid < 128) { sm.bf1v[tid] = bf1[tid]; sm.bf2v[tid] = bf2[tid]; }
    for (int idx = tid; idx < 1024; idx += NTHR) sm.bf3v[idx] = bf3[idx];
    if (tid < 64) {  // x0 = coeff_a[:,0,:]
        int b = tid >> 4, d = tid & 15;
        sm.dx[b][d] = coeff_a[(b0 + b) * 63 * 16 + d];
    }
    __syncthreads();

    // ---- y0 = softplus(x0 @ Wi1^T + bi1) @ Wi2^T + bi2 ----
    {
        int b = tid >> 6;
        float* h1f = reinterpret_cast<float*>(sm.h1d);
        #pragma unroll
        for (int q = 0; q < 2; ++q) {
            int j = ((tid & 63) << 1) + q;
            float acc = bi1[j];
            #pragma unroll
            for (int d = 0; d < 16; ++d) acc += sm.dx[b][d] * Wi1[j * 16 + d];
            h1f[b * 128 + j] = softplus_f(acc);
        }
    }
    __syncthreads();
    {
        int b = tid >> 6, s = tid & 63;
        const float* h1f = reinterpret_cast<const float*>(sm.h1d);
        float acc = bi2[s];
        #pragma unroll 8
        for (int k = 0; k < 128; ++k) acc += h1f[b * 128 + k] * Wi2[s * 128 + k];
        sm.y[b][s] = acc;
    }
    __syncthreads();
    if (tid < 32) {  // out[:, 0, :]
        int b = tid >> 3, o = tid & 7;
        float acc = br[o];
        #pragma unroll 8
        for (int s2 = 0; s2 < 64; ++s2) acc += sm.y[b][s2] * Wr[o * 64 + s2];
        out[((b0 + b) * 64 + 0) * 8 + o] = acc;
    }

    // ---- time loop: 63 steps x 6 stages (stage 7 dead: B_SOL[6]=0) ----
    for (int t = 0; t < 63; ++t) {
        float h = ts[t + 1] - ts[t];
        if (tid < 64) {
            int b = tid >> 4, d = tid & 15;
            int base = ((b0 + b) * 63 + t) * 16 + d;
            sm.cbv[b][d] = coeff_b[base];
            sm.ccv[b][d] = coeff_c[base];
            sm.cdv[b][d] = coeff_d[base];
        }
        __syncthreads();

        #pragma unroll
        for (int j = 0; j < 6; ++j) {
            if (tid < 64) {  // dxdt
                int b = tid >> 4, d = tid & 15;
                float fr = cC[j] * h;
                sm.dx[b][d] = sm.cbv[b][d] + fr * (2.0f * sm.ccv[b][d] + 3.0f * fr * sm.cdv[b][d]);
            }
            {  // yj = y + h * sum_m A[j][m] * ks[m]
                int b = tid >> 6, s = tid & 63;
                float v = sm.y[b][s];
                #pragma unroll
                for (int m = 0; m < 5; ++m)
                    if (m < j) v += h * cA[j][m] * sm.ks[m][b][s];
                sm.yjd[b][s] = dup2(v);
            }
            __syncthreads();

            // GEMM1: h1 = softplus(yj @ Wf1^T + bf1)  [4 x 128, K=64]
            {
                int b = tid >> 6, p = tid & 63;
                const unsigned long long* w =
                    reinterpret_cast<const unsigned long long*>(sm.Wf1T);
                unsigned long long acc = 0ull;
                #pragma unroll 8
                for (int s2 = 0; s2 < 64; ++s2) acc = fma2(sm.yjd[b][s2], w[s2 * 64 + p], acc);
                float2 a = u2f(acc);
                int i = p << 1;
                sm.h1d[b][i]     = dup2(softplus_f(a.x + sm.bf1v[i]));
                sm.h1d[b][i + 1] = dup2(softplus_f(a.y + sm.bf1v[i + 1]));
            }
            __syncthreads();

            // GEMM2: h2 = softplus(h1 @ Wf2^T + bf2)  [4 x 128, K=128]
            {
                int b = tid >> 6, p = tid & 63;
                const unsigned long long* w =
                    reinterpret_cast<const unsigned long long*>(sm.Wf2T);
                unsigned long long acc = 0ull;
                #pragma unroll 8
                for (int k = 0; k < 128; ++k) acc = fma2(sm.h1d[b][k], w[k * 64 + p], acc);
                float2 a = u2f(acc);
                int i = p << 1;
                sm.h2d[b][i]     = dup2(softplus_f(a.x + sm.bf2v[i]));
                sm.h2d[b][i + 1] = dup2(softplus_f(a.y + sm.bf2v[i + 1]));
            }
            __syncthreads();

            // GEMM3 + einsum: thread owns n = 4*tid..4*tid+3 for all 4 rows
            {
                unsigned long long a00 = 0, a01 = 0, a10 = 0, a11 = 0;
                unsigned long long a20 = 0, a21 = 0, a30 = 0, a31 = 0;
                const float* Wp = g_Wf3T + 4 * tid;
                #pragma unroll 16
                for (int k = 0; k < 128; ++k) {
                    unsigned long long wx, wy;
                    ldg128(Wp + k * 1024, wx, wy);
                    unsigned long long h0v = sm.h2d[0][k];
                    unsigned long long h1v = sm.h2d[1][k];
                    unsigned long long h2v = sm.h2d[2][k];
                    unsigned long long h3v = sm.h2d[3][k];
                    a00 = fma2(h0v, wx, a00); a01 = fma2(h0v, wy, a01);
                    a10 = fma2(h1v, wx, a10); a11 = fma2(h1v, wy, a11);
                    a20 = fma2(h2v, wx, a20); a21 = fma2(h2v, wy, a21);
                    a30 = fma2(h3v, wx, a30); a31 = fma2(h3v, wy, a31);
                }
                int s = tid >> 2, d0 = (tid & 3) << 2;
                float bz0 = sm.bf3v[4 * tid + 0], bz1 = sm.bf3v[4 * tid + 1];
                float bz2 = sm.bf3v[4 * tid + 2], bz3 = sm.bf3v[4 * tid + 3];
                #pragma unroll
                for (int b = 0; b < 4; ++b) {
                    unsigned long long q0 = (b == 0) ? a00 : (b == 1) ? a10 : (b == 2) ? a20 : a30;
                    unsigned long long q1 = (b == 0) ? a01 : (b == 1) ? a11 : (b == 2) ? a21 : a31;
                    float2 x0 = u2f(q0), x1 = u2f(q1);
                    float v0 = tanh_fast(x0.x + bz0);
                    float v1 = tanh_fast(x0.y + bz1);
                    float v2 = tanh_fast(x1.x + bz2);
                    float v3 = tanh_fast(x1.y + bz3);
                    float p = v0 * sm.dx[b][d0] + v1 * sm.dx[b][d0 + 1] +
                              v2 * sm.dx[b][d0 + 2] + v3 * sm.dx[b][d0 + 3];
                    p += __shfl_xor_sync(0xffffffffu, p, 1);
                    p += __shfl_xor_sync(0xffffffffu, p, 2);
                    if ((tid & 3) == 0) sm.ks[j][b][s] = p;
                }
            }
            __syncthreads();
        }

        {  // y += h * sum_j B_SOL[j] * ks[j]
            int b = tid >> 6, s = tid & 63;
            float sum = 0.0f;
            #pragma unroll
            for (int j = 0; j < 6; ++j) sum += cBw[j] * sm.ks[j][b][s];
            sm.y[b][s] += h * sum;
        }
        __syncthreads();

        if (tid < 32) {  // out[:, t+1, :] = y @ Wr^T + br
            int b = tid >> 3, o = tid & 7;
            float acc = br[o];
            #pragma unroll 8
            for (int s2 = 0; s2 < 64; ++s2) acc += sm.y[b][s2] * Wr[o * 64 + s2];
            out[((b0 + b) * 64 + (t + 1)) * 8 + o] = acc;
        }
        __syncthreads();
    }
}

extern "C" void kernel_launch(void* const* d_in, const int* in_sizes, int n_in,
                              void* d_out, int out_size) {
    const float* ts      = (const float*)d_in[0];
    const float* coeff_d = (const float*)d_in[1];
    const float* coeff_c = (const float*)d_in[2];
    const float* coeff_b = (const float*)d_in[3];
    const float* coeff_a = (const float*)d_in[4];
    const float* Wi1 = (const float*)d_in[5];
    const float* bi1 = (const float*)d_in[6];
    const float* Wi2 = (const float*)d_in[7];
    const float* bi2 = (const float*)d_in[8];
    const float* Wf1 = (const float*)d_in[9];
    const float* bf1 = (const float*)d_in[10];
    const float* Wf2 = (const float*)d_in[11];
    const float* bf2 = (const float*)d_in[12];
    const float* Wf3 = (const float*)d_in[13];
    const float* bf3 = (const float*)d_in[14];
    const float* Wr  = (const float*)d_in[15];
    const float* br  = (const float*)d_in[16];
    float* out = (float*)d_out;

    static bool attr_set = false;
    if (!attr_set) {
        cudaFuncSetAttribute(cde_kernel, cudaFuncAttributeMaxDynamicSharedMemorySize,
                             (int)sizeof(Smem));
        attr_set = true;
    }

    prep_kernel<<<512, NTHR>>>(Wf3);
    cde_kernel<<<64, NTHR, sizeof(Smem)>>>(ts, coeff_d, coeff_c, coeff_b, coeff_a,
                                           Wi1, bi1, Wi2, bi2, Wf1, bf1, Wf2, bf2,
                                           bf3, Wr, br, out);
}

// round 4
// speedup vs baseline: 1.2589x; 1.2589x over previous
#include <cuda_runtime.h>
#include <math.h>
#include <cstddef>

// B=256, T=64, D=16, S=64, H=128, O=8
#define NTHR 256
#define KC   56   // k-rows of the Wf3 half cached in SMEM (of 128)

// Pre-transposed Wf3: g_Wf3T[k*1024+n] = Wf3[n*128+k]  (512 KB, L2-resident)
__device__ __align__(16) float g_Wf3T[128 * 1024];

__constant__ float cC[6]  = {0.0f, 0.161f, 0.327f, 0.9f, 0.9800255409045097f, 1.0f};
__constant__ float cBw[6] = {0.09646076681806523f, 0.01f, 0.4798896504144996f,
                             1.379008574103742f, -3.290069515436081f, 2.324710524099774f};
__constant__ float cA[6][5] = {
    {0.f, 0.f, 0.f, 0.f, 0.f},
    {0.161f, 0.f, 0.f, 0.f, 0.f},
    {-0.008480655492356989f, 0.335480655492357f, 0.f, 0.f, 0.f},
    {2.8971530571054935f, -6.359448489975075f, 4.3622954328695815f, 0.f, 0.f},
    {5.325864828439257f, -11.748883564062828f, 7.4955393428898365f, -0.09249506636175525f, 0.f},
    {5.86145544294642f, -12.92096931784711f, 8.159367898576159f, -0.071584973281401f,
     -0.028269050394068383f}};

struct Smem {
    float wc[KC * 512];               // cached Wf3 half: [k][n_local], 114688 B
    float Wf2T[128 * 128];            // [k][i]   65536 B
    float Wf1T[64 * 128];             // [s][i]   32768 B
    unsigned long long h2d[4][128];   // dup-pair h2, ALL 4 rows (exchanged)  4096 B
    unsigned long long h1d[2][128];   // dup-pair h1, 2 local rows            2048 B
    unsigned long long yjd[2][64];    // dup-pair yj, 2 local rows            1024 B
    float y[4][64];                   // replicated                           1024 B
    float ks[6][4][64];               // replicated (via exchange)            6144 B
    float dx[4][16];                  //                                      256 B
    float cbv[4][16];
    float ccv[4][16];
    float cdv[4][16];
    float bf1v[128];
    float bf2v[128];
    float bf3loc[512];                // bias slice for this CTA's n-half
    unsigned long long h2_mbar;
    unsigned long long ks_mbar;
};  // total 231440 B  (< 232448 opt-in limit)

// ---------- helpers ----------
__device__ __forceinline__ unsigned long long fma2(unsigned long long a,
                                                   unsigned long long b,
                                                   unsigned long long c) {
    unsigned long long d;
    asm("fma.rn.f32x2 %0, %1, %2, %3;" : "=l"(d) : "l"(a), "l"(b), "l"(c));
    return d;
}
__device__ __forceinline__ unsigned long long dup2(float v) {
    unsigned long long r;
    asm("mov.b64 %0, {%1, %1};" : "=l"(r) : "f"(v));
    return r;
}
__device__ __forceinline__ float2 u2f(unsigned long long v) {
    float2 r;
    asm("mov.b64 {%0, %1}, %2;" : "=f"(r.x), "=f"(r.y) : "l"(v));
    return r;
}
__device__ __forceinline__ unsigned long long ldg64(const float* p) {
    unsigned long long v;
    asm("ld.global.nc.u64 %0, [%1];" : "=l"(v) : "l"(p));
    return v;
}
__device__ __forceinline__ unsigned smem_u32(const void* p) {
    unsigned r;
    asm("{ .reg .u64 t; cvta.to.shared.u64 t, %1; cvt.u32.u64 %0, t; }"
        : "=r"(r) : "l"(p));
    return r;
}
__device__ __forceinline__ unsigned long long lds64(unsigned a) {
    unsigned long long v;
    asm("ld.shared.u64 %0, [%1];" : "=l"(v) : "r"(a));
    return v;
}
__device__ __forceinline__ void lds_v2u64(unsigned a, unsigned long long& x,
                                          unsigned long long& y) {
    asm("ld.shared.v2.u64 {%0, %1}, [%2];" : "=l"(x), "=l"(y) : "r"(a));
}
__device__ __forceinline__ unsigned mapa_u32(unsigned laddr, unsigned peer) {
    unsigned r;
    asm("mapa.shared::cluster.u32 %0, %1, %2;" : "=r"(r) : "r"(laddr), "r"(peer));
    return r;
}
__device__ __forceinline__ void mbar_init(unsigned a, unsigned cnt) {
    asm volatile("mbarrier.init.shared.b64 [%0], %1;" :: "r"(a), "r"(cnt) : "memory");
}
__device__ __forceinline__ void mbar_expect_tx(unsigned a, unsigned bytes) {
    asm volatile("mbarrier.arrive.expect_tx.shared.b64 _, [%0], %1;"
                 :: "r"(a), "r"(bytes) : "memory");
}
__device__ __forceinline__ void mbar_wait(unsigned a, unsigned parity) {
    asm volatile(
        "{\n\t.reg .pred P;\n"
        "LW_%=:\n\t"
        "mbarrier.try_wait.parity.acquire.cta.shared::cta.b64 P, [%0], %1, 0x989680;\n\t"
        "@P bra LD_%=;\n\t"
        "bra LW_%=;\n"
        "LD_%=:\n\t}"
        :: "r"(a), "r"(parity) : "memory");
}
__device__ __forceinline__ void st_async64(unsigned dst, unsigned long long v, unsigned mbar) {
    asm volatile("st.async.shared::cluster.mbarrier::complete_tx::bytes.b64 [%0], %1, [%2];"
                 :: "r"(dst), "l"(v), "r"(mbar) : "memory");
}
__device__ __forceinline__ void st_async32(unsigned dst, float v, unsigned mbar) {
    asm volatile("st.async.shared::cluster.mbarrier::complete_tx::bytes.b32 [%0], %1, [%2];"
                 :: "r"(dst), "f"(v), "r"(mbar) : "memory");
}
__device__ __forceinline__ float softplus_f(float x) {
    return fmaxf(x, 0.0f) + log1pf(__expf(-fabsf(x)));
}
__device__ __forceinline__ float tanh_fast(float x) {
    float e = __expf(2.0f * x);
    return 1.0f - 2.0f / (e + 1.0f);
}

__global__ void __launch_bounds__(NTHR, 1) prep_kernel(const float* __restrict__ Wf3) {
    int idx = blockIdx.x * NTHR + threadIdx.x;  // 512 blocks
    int k = idx >> 10;
    int n = idx & 1023;
    g_Wf3T[idx] = Wf3[n * 128 + k];
}

__global__ void __launch_bounds__(NTHR, 1) __cluster_dims__(2, 1, 1) cde_kernel(
    const float* __restrict__ ts,
    const float* __restrict__ coeff_d, const float* __restrict__ coeff_c,
    const float* __restrict__ coeff_b, const float* __restrict__ coeff_a,
    const float* __restrict__ Wi1, const float* __restrict__ bi1,
    const float* __restrict__ Wi2, const float* __restrict__ bi2,
    const float* __restrict__ Wf1, const float* __restrict__ bf1,
    const float* __restrict__ Wf2, const float* __restrict__ bf2,
    const float* __restrict__ bf3,
    const float* __restrict__ Wr, const float* __restrict__ br,
    float* __restrict__ out)
{
    extern __shared__ char smraw[];
    Smem& sm = *reinterpret_cast<Smem*>(smraw);
    const int tid = threadIdx.x;
    unsigned rank;
    asm("mov.u32 %0, %%cluster_ctarank;" : "=r"(rank));
    const unsigned peer = rank ^ 1u;
    const int b0g = (blockIdx.x >> 1) * 4;   // 4 batch rows per cluster

    const unsigned sbase = smem_u32(smraw);
    const unsigned off_h2  = (unsigned)offsetof(Smem, h2d);
    const unsigned off_ks  = (unsigned)offsetof(Smem, ks);
    const unsigned my_h2mbar = sbase + (unsigned)offsetof(Smem, h2_mbar);
    const unsigned my_ksmbar = sbase + (unsigned)offsetof(Smem, ks_mbar);
    const unsigned peer_h2mbar = mapa_u32(my_h2mbar, peer);
    const unsigned peer_ksmbar = mapa_u32(my_ksmbar, peer);
    const unsigned peer_h2base = mapa_u32(sbase + off_h2, peer);
    const unsigned peer_ksbase = mapa_u32(sbase + off_ks, peer);

    if (tid == 0) { mbar_init(my_h2mbar, 1); mbar_init(my_ksmbar, 1); }

    // ---- one-time init ----
    for (int idx = tid; idx < 64 * 128; idx += NTHR) {
        int s = idx >> 7, i = idx & 127;
        sm.Wf1T[idx] = Wf1[i * 64 + s];
    }
    for (int idx = tid; idx < 128 * 128; idx += NTHR) {
        int k = idx >> 7, i = idx & 127;
        sm.Wf2T[idx] = Wf2[i * 128 + k];
    }
    for (int idx = tid; idx < KC * 512; idx += NTHR) {
        int k = idx >> 9, n = idx & 511;
        sm.wc[idx] = g_Wf3T[k * 1024 + rank * 512 + n];
    }
    if (tid < 128) { sm.bf1v[tid] = bf1[tid]; sm.bf2v[tid] = bf2[tid]; }
    for (int idx = tid; idx < 512; idx += NTHR) sm.bf3loc[idx] = bf3[rank * 512 + idx];
    if (tid < 64) {  // x0 = coeff_a[:,0,:]  (all 4 rows, replicated)
        int b = tid >> 4, d = tid & 15;
        sm.dx[b][d] = coeff_a[(b0g + b) * 63 * 16 + d];
    }
    __syncthreads();
    // peer mbarriers must be live before any st.async
    asm volatile("barrier.cluster.arrive.aligned;" ::: "memory");
    asm volatile("barrier.cluster.wait.aligned;" ::: "memory");

    // ---- y0 = softplus(x0 @ Wi1^T + bi1) @ Wi2^T + bi2  (replicated, 4 rows) ----
    {
        int b = tid >> 6;
        float* h1f = reinterpret_cast<float*>(sm.h1d);  // 512-float scratch
        #pragma unroll
        for (int q = 0; q < 2; ++q) {
            int j = ((tid & 63) << 1) + q;
            float acc = bi1[j];
            #pragma unroll
            for (int d = 0; d < 16; ++d) acc += sm.dx[b][d] * Wi1[j * 16 + d];
            h1f[b * 128 + j] = softplus_f(acc);
        }
    }
    __syncthreads();
    {
        int b = tid >> 6, s = tid & 63;
        const float* h1f = reinterpret_cast<const float*>(sm.h1d);
        float acc = bi2[s];
        #pragma unroll 8
        for (int k = 0; k < 128; ++k) acc += h1f[b * 128 + k] * Wi2[s * 128 + k];
        sm.y[b][s] = acc;
    }
    __syncthreads();
    if (tid < 16) {  // out[:, 0, :] for this CTA's 2 local rows
        int bl = tid >> 3, o = tid & 7;
        int row = rank * 2 + bl;
        float acc = br[o];
        #pragma unroll 8
        for (int s2 = 0; s2 < 64; ++s2) acc += sm.y[row][s2] * Wr[o * 64 + s2];
        out[((b0g + row) * 64 + 0) * 8 + o] = acc;
    }

    // GEMM3 per-thread constants: thread owns n-pair p = tid for all 4 rows
    const unsigned wc_addr0 = sbase + (unsigned)offsetof(Smem, wc) + (unsigned)tid * 8u;
    const unsigned h2_addr  = sbase + off_h2;           // + row*1024 + k*8
    const float* gW = g_Wf3T + rank * 512 + 2 * tid;    // streamed half
    const int d0 = (tid & 7) << 1;
    const int s_g = (int)rank * 32 + (tid >> 3);
    const bool writer = ((tid & 7) == 0);

    unsigned ph = 0;

    // ---- time loop: 63 steps x 6 RK stages ----
    for (int t = 0; t < 63; ++t) {
        float h = ts[t + 1] - ts[t];
        if (tid < 64) {
            int b = tid >> 4, d = tid & 15;
            int base = ((b0g + b) * 63 + t) * 16 + d;
            sm.cbv[b][d] = coeff_b[base];
            sm.ccv[b][d] = coeff_c[base];
            sm.cdv[b][d] = coeff_d[base];
        }

        #pragma unroll 1
        for (int j = 0; j < 6; ++j) {
            if (tid == 0) {
                mbar_expect_tx(my_h2mbar, 2048u);
                mbar_expect_tx(my_ksmbar, 512u);
            }
            if (tid < 64) {  // dxdt, all 4 rows
                int b = tid >> 4, d = tid & 15;
                float fr = cC[j] * h;
                sm.dx[b][d] = sm.cbv[b][d] + fr * (2.0f * sm.ccv[b][d] + 3.0f * fr * sm.cdv[b][d]);
            }
            if (tid < 128) {  // yj for 2 local rows
                int bl = tid >> 6, s = tid & 63;
                int row = (int)rank * 2 + bl;
                float v = sm.y[row][s];
                #pragma unroll
                for (int m = 0; m < 5; ++m)
                    if (m < j) v += h * cA[j][m] * sm.ks[m][row][s];
                sm.yjd[bl][s] = dup2(v);
            }
            __syncthreads();  // S1

            if (tid < 128) {  // GEMM1: 2 rows, K=64
                int bl = tid >> 6, p = tid & 63;
                const unsigned long long* w =
                    reinterpret_cast<const unsigned long long*>(sm.Wf1T);
                unsigned long long acc = 0ull;
                #pragma unroll 8
                for (int s2 = 0; s2 < 64; ++s2) acc = fma2(sm.yjd[bl][s2], w[s2 * 64 + p], acc);
                float2 a = u2f(acc);
                int i = p << 1;
                sm.h1d[bl][i]     = dup2(softplus_f(a.x + sm.bf1v[i]));
                sm.h1d[bl][i + 1] = dup2(softplus_f(a.y + sm.bf1v[i + 1]));
            }
            __syncthreads();  // S2

            if (tid < 128) {  // GEMM2: 2 rows, K=128; store local + send to peer
                int bl = tid >> 6, p = tid & 63;
                int row = (int)rank * 2 + bl;
                const unsigned long long* w =
                    reinterpret_cast<const unsigned long long*>(sm.Wf2T);
                unsigned long long acc = 0ull;
                #pragma unroll 8
                for (int k = 0; k < 128; ++k) acc = fma2(sm.h1d[bl][k], w[k * 64 + p], acc);
                float2 a = u2f(acc);
                int i = p << 1;
                unsigned long long v0 = dup2(softplus_f(a.x + sm.bf2v[i]));
                unsigned long long v1 = dup2(softplus_f(a.y + sm.bf2v[i + 1]));
                sm.h2d[row][i]     = v0;
                sm.h2d[row][i + 1] = v1;
                unsigned rdst = peer_h2base + (unsigned)(row * 128 + i) * 8u;
                st_async64(rdst,      v0, peer_h2mbar);
                st_async64(rdst + 8u, v1, peer_h2mbar);
            }
            __syncthreads();            // S3: local h2 halves visible
            mbar_wait(my_h2mbar, ph);   // peer h2 halves arrived

            // GEMM3: 4 rows x (n-pair tid) over K=128 (56 from SMEM, 72 from L2)
            unsigned long long a0 = 0, a1 = 0, a2 = 0, a3 = 0;
            #pragma unroll 4
            for (int k = 0; k < KC; k += 2) {
                unsigned long long w0 = lds64(wc_addr0 + (unsigned)k * 2048u);
                unsigned long long w1 = lds64(wc_addr0 + (unsigned)(k + 1) * 2048u);
                unsigned long long h0x, h0y, h1x, h1y, h2x, h2y, h3x, h3y;
                lds_v2u64(h2_addr +            (unsigned)k * 8u, h0x, h0y);
                lds_v2u64(h2_addr + 1024u +    (unsigned)k * 8u, h1x, h1y);
                lds_v2u64(h2_addr + 2048u +    (unsigned)k * 8u, h2x, h2y);
                lds_v2u64(h2_addr + 3072u +    (unsigned)k * 8u, h3x, h3y);
                a0 = fma2(h0x, w0, a0); a0 = fma2(h0y, w1, a0);
                a1 = fma2(h1x, w0, a1); a1 = fma2(h1y, w1, a1);
                a2 = fma2(h2x, w0, a2); a2 = fma2(h2y, w1, a2);
                a3 = fma2(h3x, w0, a3); a3 = fma2(h3y, w1, a3);
            }
            #pragma unroll 1
            for (int kb = KC; kb < 128; kb += 8) {   // 9 chunks of 8
                unsigned long long wv[8];
                #pragma unroll
                for (int kk = 0; kk < 8; ++kk) wv[kk] = ldg64(gW + (kb + kk) * 1024);
                #pragma unroll
                for (int kk = 0; kk < 8; kk += 2) {
                    int k = kb + kk;
                    unsigned long long h0x, h0y, h1x, h1y, h2x, h2y, h3x, h3y;
                    lds_v2u64(h2_addr +         (unsigned)k * 8u, h0x, h0y);
                    lds_v2u64(h2_addr + 1024u + (unsigned)k * 8u, h1x, h1y);
                    lds_v2u64(h2_addr + 2048u + (unsigned)k * 8u, h2x, h2y);
                    lds_v2u64(h2_addr + 3072u + (unsigned)k * 8u, h3x, h3y);
                    a0 = fma2(h0x, wv[kk], a0); a0 = fma2(h0y, wv[kk + 1], a0);
                    a1 = fma2(h1x, wv[kk], a1); a1 = fma2(h1y, wv[kk + 1], a1);
                    a2 = fma2(h2x, wv[kk], a2); a2 = fma2(h2y, wv[kk + 1], a2);
                    a3 = fma2(h3x, wv[kk], a3); a3 = fma2(h3y, wv[kk + 1], a3);
                }
            }
            // epilogue: tanh + einsum partial + 8-lane reduce
            float z0 = sm.bf3loc[2 * tid], z1 = sm.bf3loc[2 * tid + 1];
            float kv[4];
            {
                unsigned long long aa[4] = {a0, a1, a2, a3};
                #pragma unroll
                for (int b = 0; b < 4; ++b) {
                    float2 f = u2f(aa[b]);
                    float v0 = tanh_fast(f.x + z0);
                    float v1 = tanh_fast(f.y + z1);
                    float p = v0 * sm.dx[b][d0] + v1 * sm.dx[b][d0 + 1];
                    p += __shfl_xor_sync(0xffffffffu, p, 1);
                    p += __shfl_xor_sync(0xffffffffu, p, 2);
                    p += __shfl_xor_sync(0xffffffffu, p, 4);
                    kv[b] = p;
                }
            }
            if (writer) {
                #pragma unroll
                for (int b = 0; b < 4; ++b) sm.ks[j][b][s_g] = kv[b];
            }
            __syncthreads();  // S4: all GEMM3 reads of h2d done; local ks visible
            if (writer) {
                #pragma unroll
                for (int b = 0; b < 4; ++b) {
                    unsigned rdst = peer_ksbase + (unsigned)(((j * 4 + b) * 64) + s_g) * 4u;
                    st_async32(rdst, kv[b], peer_ksmbar);
                }
            }
            mbar_wait(my_ksmbar, ph);  // peer ks half arrived
            ph ^= 1;
        }

        {  // y += h * sum_j B_SOL[j] * ks[j]   (replicated, all 4 rows)
            int b = tid >> 6, s = tid & 63;
            float sum = 0.0f;
            #pragma unroll
            for (int j = 0; j < 6; ++j) sum += cBw[j] * sm.ks[j][b][s];
            sm.y[b][s] += h * sum;
        }
        __syncthreads();  // S5

        if (tid < 16) {  // out[:, t+1, :] for 2 local rows
            int bl = tid >> 3, o = tid & 7;
            int row = (int)rank * 2 + bl;
            float acc = br[o];
            #pragma unroll 8
            for (int s2 = 0; s2 < 64; ++s2) acc += sm.y[row][s2] * Wr[o * 64 + s2];
            out[((b0g + row) * 64 + (t + 1)) * 8 + o] = acc;
        }
    }
}

extern "C" void kernel_launch(void* const* d_in, const int* in_sizes, int n_in,
                              void* d_out, int out_size) {
    const float* ts      = (const float*)d_in[0];
    const float* coeff_d = (const float*)d_in[1];
    const float* coeff_c = (const float*)d_in[2];
    const float* coeff_b = (const float*)d_in[3];
    const float* coeff_a = (const float*)d_in[4];
    const float* Wi1 = (const float*)d_in[5];
    const float* bi1 = (const float*)d_in[6];
    const float* Wi2 = (const float*)d_in[7];
    const float* bi2 = (const float*)d_in[8];
    const float* Wf1 = (const float*)d_in[9];
    const float* bf1 = (const float*)d_in[10];
    const float* Wf2 = (const float*)d_in[11];
    const float* bf2 = (const float*)d_in[12];
    const float* Wf3 = (const float*)d_in[13];
    const float* bf3 = (const float*)d_in[14];
    const float* Wr  = (const float*)d_in[15];
    const float* br  = (const float*)d_in[16];
    float* out = (float*)d_out;

    cudaFuncSetAttribute(cde_kernel, cudaFuncAttributeMaxDynamicSharedMemorySize,
                         (int)sizeof(Smem));

    prep_kernel<<<512, NTHR>>>(Wf3);
    cde_kernel<<<128, NTHR, sizeof(Smem)>>>(ts, coeff_d, coeff_c, coeff_b, coeff_a,
                                            Wi1, bi1, Wi2, bi2, Wf1, bf1, Wf2, bf2,
                                            bf3, Wr, br, out);
}

// round 7
// speedup vs baseline: 1.3442x; 1.0678x over previous
#include <cuda_runtime.h>
#include <math.h>
#include <cstddef>

// B=256, T=64, D=16, S=64, H=128, O=8
#define NTHR 256
#define KC   56   // k-rows of the Wf3 half cached in SMEM (of 128)

// Pre-transposed Wf3: g_Wf3T[k*1024+n] = Wf3[n*128+k]  (512 KB, L2-resident)
__device__ __align__(16) float g_Wf3T[128 * 1024];

__constant__ float cC[6]  = {0.0f, 0.161f, 0.327f, 0.9f, 0.9800255409045097f, 1.0f};
__constant__ float cBw[6] = {0.09646076681806523f, 0.01f, 0.4798896504144996f,
                             1.379008574103742f, -3.290069515436081f, 2.324710524099774f};
__constant__ float cA[6][5] = {
    {0.f, 0.f, 0.f, 0.f, 0.f},
    {0.161f, 0.f, 0.f, 0.f, 0.f},
    {-0.008480655492356989f, 0.335480655492357f, 0.f, 0.f, 0.f},
    {2.8971530571054935f, -6.359448489975075f, 4.3622954328695815f, 0.f, 0.f},
    {5.325864828439257f, -11.748883564062828f, 7.4955393428898365f, -0.09249506636175525f, 0.f},
    {5.86145544294642f, -12.92096931784711f, 8.159367898576159f, -0.071584973281401f,
     -0.028269050394068383f}};

struct Smem {
    float wc[KC * 512];               // cached Wf3 half: [k][n_local], 114688 B
    float Wf2T[128 * 128];            // [k][i]
    float Wf1T[64 * 128];             // [s][i]
    unsigned long long h2d[4][128];   // dup-pair h2, ALL 4 rows (exchanged)
    unsigned long long h1d[2][128];   // dup-pair h1, 2 local rows
    unsigned long long yjd[2][64];    // dup-pair yj, 2 local rows
    float y[4][64];                   // replicated
    float ks[6][4][64];               // replicated (via exchange)
    float dx[4][16];
    float cbv[4][16];
    float ccv[4][16];
    float cdv[4][16];
    float bf1v[128];
    float bf2v[128];
    float bf3loc[512];                // bias slice for this CTA's n-half
    unsigned long long h2_mbar;
    unsigned long long ks_mbar;
};  // total 231440 B

// ---------- helpers ----------
__device__ __forceinline__ unsigned long long fma2(unsigned long long a,
                                                   unsigned long long b,
                                                   unsigned long long c) {
    unsigned long long d;
    asm("fma.rn.f32x2 %0, %1, %2, %3;" : "=l"(d) : "l"(a), "l"(b), "l"(c));
    return d;
}
__device__ __forceinline__ unsigned long long dup2(float v) {
    unsigned long long r;
    asm("mov.b64 %0, {%1, %1};" : "=l"(r) : "f"(v));
    return r;
}
__device__ __forceinline__ float2 u2f(unsigned long long v) {
    float2 r;
    asm("mov.b64 {%0, %1}, %2;" : "=f"(r.x), "=f"(r.y) : "l"(v));
    return r;
}
__device__ __forceinline__ unsigned long long ldg64(const float* p) {
    unsigned long long v;
    asm("ld.global.nc.u64 %0, [%1];" : "=l"(v) : "l"(p));
    return v;
}
__device__ __forceinline__ unsigned smem_u32(const void* p) {
    unsigned r;
    asm("{ .reg .u64 t; cvta.to.shared.u64 t, %1; cvt.u32.u64 %0, t; }"
        : "=r"(r) : "l"(p));
    return r;
}
__device__ __forceinline__ unsigned long long lds64(unsigned a) {
    unsigned long long v;
    asm("ld.shared.u64 %0, [%1];" : "=l"(v) : "r"(a));
    return v;
}
// volatile: h2 tile reads must stay after the mbarrier wait
__device__ __forceinline__ void lds_v2u64(unsigned a, unsigned long long& x,
                                          unsigned long long& y) {
    asm volatile("ld.shared.v2.u64 {%0, %1}, [%2];" : "=l"(x), "=l"(y) : "r"(a));
}
__device__ __forceinline__ unsigned mapa_u32(unsigned laddr, unsigned peer) {
    unsigned r;
    asm("mapa.shared::cluster.u32 %0, %1, %2;" : "=r"(r) : "r"(laddr), "r"(peer));
    return r;
}
__device__ __forceinline__ void mbar_init(unsigned a, unsigned cnt) {
    asm volatile("mbarrier.init.shared.b64 [%0], %1;" :: "r"(a), "r"(cnt) : "memory");
}
__device__ __forceinline__ void mbar_expect_tx(unsigned a, unsigned bytes) {
    asm volatile("mbarrier.arrive.expect_tx.shared.b64 _, [%0], %1;"
                 :: "r"(a), "r"(bytes) : "memory");
}
__device__ __forceinline__ void mbar_wait(unsigned a, unsigned parity) {
    asm volatile(
        "{\n\t.reg .pred P;\n"
        "LW_%=:\n\t"
        "mbarrier.try_wait.parity.acquire.cta.shared::cta.b64 P, [%0], %1, 0x989680;\n\t"
        "@P bra LD_%=;\n\t"
        "bra LW_%=;\n"
        "LD_%=:\n\t}"
        :: "r"(a), "r"(parity) : "memory");
}
__device__ __forceinline__ void st_async64(unsigned dst, unsigned long long v, unsigned mbar) {
    asm volatile("st.async.shared::cluster.mbarrier::complete_tx::bytes.b64 [%0], %1, [%2];"
                 :: "r"(dst), "l"(v), "r"(mbar) : "memory");
}
__device__ __forceinline__ void st_async32(unsigned dst, float v, unsigned mbar) {
    asm volatile("st.async.shared::cluster.mbarrier::complete_tx::bytes.b32 [%0], %1, [%2];"
                 :: "r"(dst), "f"(v), "r"(mbar) : "memory");
}
__device__ __forceinline__ float softplus_f(float x) {
    return fmaxf(x, 0.0f) + log1pf(__expf(-fabsf(x)));
}
__device__ __forceinline__ float tanh_fast(float x) {
    float e = __expf(2.0f * x);
    return 1.0f - 2.0f / (e + 1.0f);
}

// GEMM3 streamed-weight pipeline helpers (weights are constant -> free to issue early)
__device__ __forceinline__ void g3_issue(unsigned long long* wv, const float* gW, int q) {
    const float* gq = gW + (KC + 8 * q) * 1024;
    #pragma unroll
    for (int i = 0; i < 8; ++i) wv[i] = ldg64(gq + i * 1024);
}
__device__ __forceinline__ void g3_consume(const unsigned long long* wv, unsigned h2_addr, int q,
                                           unsigned long long& a0, unsigned long long& a1,
                                           unsigned long long& a2, unsigned long long& a3) {
    unsigned hk0 = h2_addr + (unsigned)(KC + 8 * q) * 8u;
    #pragma unroll
    for (int kk = 0; kk < 8; kk += 2) {
        unsigned hk = hk0 + (unsigned)kk * 8u;
        unsigned long long h0x, h0y, h1x, h1y, h2x, h2y, h3x, h3y;
        lds_v2u64(hk,          h0x, h0y);
        lds_v2u64(hk + 1024u,  h1x, h1y);
        lds_v2u64(hk + 2048u,  h2x, h2y);
        lds_v2u64(hk + 3072u,  h3x, h3y);
        a0 = fma2(h0x, wv[kk], a0); a0 = fma2(h0y, wv[kk + 1], a0);
        a1 = fma2(h1x, wv[kk], a1); a1 = fma2(h1y, wv[kk + 1], a1);
        a2 = fma2(h2x, wv[kk], a2); a2 = fma2(h2y, wv[kk + 1], a2);
        a3 = fma2(h3x, wv[kk], a3); a3 = fma2(h3y, wv[kk + 1], a3);
    }
}
__device__ __forceinline__ void g3_cached(unsigned wc_addr0, unsigned h2_addr, int k0, int k1,
                                          unsigned long long& a0, unsigned long long& a1,
                                          unsigned long long& a2, unsigned long long& a3) {
    unsigned wA = wc_addr0 + (unsigned)k0 * 2048u;
    unsigned hA = h2_addr + (unsigned)k0 * 8u;
    #pragma unroll 14
    for (int k = k0; k < k1; k += 2) {
        unsigned long long w0 = lds64(wA);
        unsigned long long w1 = lds64(wA + 2048u);
        wA += 4096u;
        unsigned long long h0x, h0y, h1x, h1y, h2x, h2y, h3x, h3y;
        lds_v2u64(hA,          h0x, h0y);
        lds_v2u64(hA + 1024u,  h1x, h1y);
        lds_v2u64(hA + 2048u,  h2x, h2y);
        lds_v2u64(hA + 3072u,  h3x, h3y);
        hA += 16u;
        a0 = fma2(h0x, w0, a0); a0 = fma2(h0y, w1, a0);
        a1 = fma2(h1x, w0, a1); a1 = fma2(h1y, w1, a1);
        a2 = fma2(h2x, w0, a2); a2 = fma2(h2y, w1, a2);
        a3 = fma2(h3x, w0, a3); a3 = fma2(h3y, w1, a3);
    }
}

__global__ void __launch_bounds__(NTHR, 1) prep_kernel(const float* __restrict__ Wf3) {
    int idx = blockIdx.x * NTHR + threadIdx.x;  // 512 blocks
    int k = idx >> 10;
    int n = idx & 1023;
    g_Wf3T[idx] = Wf3[n * 128 + k];
}

__global__ void __launch_bounds__(NTHR, 1) __cluster_dims__(2, 1, 1) cde_kernel(
    const float* __restrict__ ts,
    const float* __restrict__ coeff_d, const float* __restrict__ coeff_c,
    const float* __restrict__ coeff_b, const float* __restrict__ coeff_a,
    const float* __restrict__ Wi1, const float* __restrict__ bi1,
    const float* __restrict__ Wi2, const float* __restrict__ bi2,
    const float* __restrict__ Wf1, const float* __restrict__ bf1,
    const float* __restrict__ Wf2, const float* __restrict__ bf2,
    const float* __restrict__ bf3,
    const float* __restrict__ Wr, const float* __restrict__ br,
    float* __restrict__ out)
{
    extern __shared__ char smraw[];
    Smem& sm = *reinterpret_cast<Smem*>(smraw);
    const int tid = threadIdx.x;
    unsigned rank;
    asm("mov.u32 %0, %%cluster_ctarank;" : "=r"(rank));
    const unsigned peer = rank ^ 1u;
    const int b0g = (blockIdx.x >> 1) * 4;   // 4 batch rows per cluster

    const unsigned sbase = smem_u32(smraw);
    const unsigned off_h2  = (unsigned)offsetof(Smem, h2d);
    const unsigned off_ks  = (unsigned)offsetof(Smem, ks);
    const unsigned my_h2mbar = sbase + (unsigned)offsetof(Smem, h2_mbar);
    const unsigned my_ksmbar = sbase + (unsigned)offsetof(Smem, ks_mbar);
    const unsigned peer_h2mbar = mapa_u32(my_h2mbar, peer);
    const unsigned peer_ksmbar = mapa_u32(my_ksmbar, peer);
    const unsigned peer_h2base = mapa_u32(sbase + off_h2, peer);
    const unsigned peer_ksbase = mapa_u32(sbase + off_ks, peer);

    if (tid == 0) { mbar_init(my_h2mbar, 1); mbar_init(my_ksmbar, 1); }

    // ---- one-time init ----
    for (int idx = tid; idx < 64 * 128; idx += NTHR) {
        int s = idx >> 7, i = idx & 127;
        sm.Wf1T[idx] = Wf1[i * 64 + s];
    }
    for (int idx = tid; idx < 128 * 128; idx += NTHR) {
        int k = idx >> 7, i = idx & 127;
        sm.Wf2T[idx] = Wf2[i * 128 + k];
    }
    for (int idx = tid; idx < KC * 512; idx += NTHR) {
        int k = idx >> 9, n = idx & 511;
        sm.wc[idx] = g_Wf3T[k * 1024 + rank * 512 + n];
    }
    if (tid < 128) { sm.bf1v[tid] = bf1[tid]; sm.bf2v[tid] = bf2[tid]; }
    for (int idx = tid; idx < 512; idx += NTHR) sm.bf3loc[idx] = bf3[rank * 512 + idx];
    if (tid < 64) {  // x0 = coeff_a[:,0,:]  (all 4 rows, replicated)
        int b = tid >> 4, d = tid & 15;
        sm.dx[b][d] = coeff_a[(b0g + b) * 63 * 16 + d];
    }
    __syncthreads();
    // peer mbarriers must be live before any st.async
    asm volatile("barrier.cluster.arrive.aligned;" ::: "memory");
    asm volatile("barrier.cluster.wait.aligned;" ::: "memory");

    // ---- y0 = softplus(x0 @ Wi1^T + bi1) @ Wi2^T + bi2  (replicated, 4 rows) ----
    {
        int b = tid >> 6;
        float* h1f = reinterpret_cast<float*>(sm.h1d);  // 512-float scratch
        #pragma unroll
        for (int q = 0; q < 2; ++q) {
            int j = ((tid & 63) << 1) + q;
            float acc = bi1[j];
            #pragma unroll
            for (int d = 0; d < 16; ++d) acc += sm.dx[b][d] * Wi1[j * 16 + d];
            h1f[b * 128 + j] = softplus_f(acc);
        }
    }
    __syncthreads();
    {
        int b = tid >> 6, s = tid & 63;
        const float* h1f = reinterpret_cast<const float*>(sm.h1d);
        float acc = bi2[s];
        #pragma unroll 8
        for (int k = 0; k < 128; ++k) acc += h1f[b * 128 + k] * Wi2[s * 128 + k];
        sm.y[b][s] = acc;
    }
    __syncthreads();
    if (tid < 16) {  // out[:, 0, :] for this CTA's 2 local rows
        int bl = tid >> 3, o = tid & 7;
        int row = rank * 2 + bl;
        float acc = br[o];
        #pragma unroll 8
        for (int s2 = 0; s2 < 64; ++s2) acc += sm.y[row][s2] * Wr[o * 64 + s2];
        out[((b0g + row) * 64 + 0) * 8 + o] = acc;
    }

    // GEMM3 per-thread constants: thread owns n-pair p = tid for all 4 rows
    const unsigned wc_addr0 = sbase + (unsigned)offsetof(Smem, wc) + (unsigned)tid * 8u;
    const unsigned h2_addr  = sbase + off_h2;           // + row*1024 + k*8
    const float* gW = g_Wf3T + rank * 512 + 2 * tid;    // streamed half
    const int d0 = (tid & 7) << 1;
    const int s_g = (int)rank * 32 + (tid >> 3);
    const bool writer = ((tid & 7) == 0);

    unsigned ph = 0;

    // ---- time loop: 63 steps x 6 RK stages ----
    for (int t = 0; t < 63; ++t) {
        float h = ts[t + 1] - ts[t];
        if (tid < 64) {
            int b = tid >> 4, d = tid & 15;
            int base = ((b0g + b) * 63 + t) * 16 + d;
            sm.cbv[b][d] = coeff_b[base];
            sm.ccv[b][d] = coeff_c[base];
            sm.cdv[b][d] = coeff_d[base];
        }

        #pragma unroll 1
        for (int j = 0; j < 6; ++j) {
            if (tid == 0) {
                mbar_expect_tx(my_h2mbar, 2048u);
                mbar_expect_tx(my_ksmbar, 512u);
            }
            if (tid < 64) {  // dxdt, all 4 rows
                int b = tid >> 4, d = tid & 15;
                float fr = cC[j] * h;
                sm.dx[b][d] = sm.cbv[b][d] + fr * (2.0f * sm.ccv[b][d] + 3.0f * fr * sm.cdv[b][d]);
            }
            if (tid < 128) {  // yj for 2 local rows
                int bl = tid >> 6, s = tid & 63;
                int row = (int)rank * 2 + bl;
                float v = sm.y[row][s];
                #pragma unroll
                for (int m = 0; m < 5; ++m)
                    if (m < j) v += h * cA[j][m] * sm.ks[m][row][s];
                sm.yjd[bl][s] = dup2(v);
            }
            __syncthreads();  // S1

            // prefetch first two streamed-weight batches (constant data, no deps);
            // their latency hides under GEMM1 + GEMM2 + barriers
            unsigned long long wv0[8], wv1[8];
            g3_issue(wv0, gW, 0);
            g3_issue(wv1, gW, 1);

            if (tid < 128) {  // GEMM1: 2 rows, K=64
                int bl = tid >> 6, pp = tid & 63;
                const unsigned long long* w =
                    reinterpret_cast<const unsigned long long*>(sm.Wf1T);
                unsigned long long acc = 0ull;
                #pragma unroll 8
                for (int s2 = 0; s2 < 64; ++s2) acc = fma2(sm.yjd[bl][s2], w[s2 * 64 + pp], acc);
                float2 a = u2f(acc);
                int i = pp << 1;
                sm.h1d[bl][i]     = dup2(softplus_f(a.x + sm.bf1v[i]));
                sm.h1d[bl][i + 1] = dup2(softplus_f(a.y + sm.bf1v[i + 1]));
            }
            __syncthreads();  // S2

            if (tid < 128) {  // GEMM2: 2 rows, K=128; store local + send to peer
                int bl = tid >> 6, pp = tid & 63;
                int row = (int)rank * 2 + bl;
                const unsigned long long* w =
                    reinterpret_cast<const unsigned long long*>(sm.Wf2T);
                unsigned long long acc = 0ull;
                #pragma unroll 8
                for (int k = 0; k < 128; ++k) acc = fma2(sm.h1d[bl][k], w[k * 64 + pp], acc);
                float2 a = u2f(acc);
                int i = pp << 1;
                unsigned long long v0 = dup2(softplus_f(a.x + sm.bf2v[i]));
                unsigned long long v1 = dup2(softplus_f(a.y + sm.bf2v[i + 1]));
                sm.h2d[row][i]     = v0;
                sm.h2d[row][i + 1] = v1;
                unsigned rdst = peer_h2base + (unsigned)(row * 128 + i) * 8u;
                st_async64(rdst,      v0, peer_h2mbar);
                st_async64(rdst + 8u, v1, peer_h2mbar);
            }
            __syncthreads();            // S3: local h2 halves visible
            mbar_wait(my_h2mbar, ph);   // peer h2 halves arrived

            // GEMM3: 4 rows x (n-pair tid), K=128 = 56 cached + 72 streamed (9x8),
            // streamed batches pipelined one ahead
            unsigned long long a0 = 0, a1 = 0, a2 = 0, a3 = 0;
            g3_cached(wc_addr0, h2_addr, 0, 28, a0, a1, a2, a3);
            g3_consume(wv0, h2_addr, 0, a0, a1, a2, a3);  g3_issue(wv0, gW, 2);
            g3_cached(wc_addr0, h2_addr, 28, 56, a0, a1, a2, a3);
            g3_consume(wv1, h2_addr, 1, a0, a1, a2, a3);  g3_issue(wv1, gW, 3);
            g3_consume(wv0, h2_addr, 2, a0, a1, a2, a3);  g3_issue(wv0, gW, 4);
            g3_consume(wv1, h2_addr, 3, a0, a1, a2, a3);  g3_issue(wv1, gW, 5);
            g3_consume(wv0, h2_addr, 4, a0, a1, a2, a3);  g3_issue(wv0, gW, 6);
            g3_consume(wv1, h2_addr, 5, a0, a1, a2, a3);  g3_issue(wv1, gW, 7);
            g3_consume(wv0, h2_addr, 6, a0, a1, a2, a3);  g3_issue(wv0, gW, 8);
            g3_consume(wv1, h2_addr, 7, a0, a1, a2, a3);
            g3_consume(wv0, h2_addr, 8, a0, a1, a2, a3);

            // epilogue: tanh + einsum partial + 8-lane reduce
            float z0 = sm.bf3loc[2 * tid], z1 = sm.bf3loc[2 * tid + 1];
            float kv[4];
            {
                unsigned long long aa[4] = {a0, a1, a2, a3};
                #pragma unroll
                for (int b = 0; b < 4; ++b) {
                    float2 f = u2f(aa[b]);
                    float v0 = tanh_fast(f.x + z0);
                    float v1 = tanh_fast(f.y + z1);
                    float p = v0 * sm.dx[b][d0] + v1 * sm.dx[b][d0 + 1];
                    p += __shfl_xor_sync(0xffffffffu, p, 1);
                    p += __shfl_xor_sync(0xffffffffu, p, 2);
                    p += __shfl_xor_sync(0xffffffffu, p, 4);
                    kv[b] = p;
                }
            }
            if (writer) {
                #pragma unroll
                for (int b = 0; b < 4; ++b) sm.ks[j][b][s_g] = kv[b];
            }
            __syncthreads();  // S4: all GEMM3 reads of h2d done; local ks visible
            if (writer) {
                #pragma unroll
                for (int b = 0; b < 4; ++b) {
                    unsigned rdst = peer_ksbase + (unsigned)(((j * 4 + b) * 64) + s_g) * 4u;
                    st_async32(rdst, kv[b], peer_ksmbar);
                }
            }
            mbar_wait(my_ksmbar, ph);  // peer ks half arrived
            ph ^= 1;
        }

        {  // y += h * sum_j B_SOL[j] * ks[j]   (replicated, all 4 rows)
            int b = tid >> 6, s = tid & 63;
            float sum = 0.0f;
            #pragma unroll
            for (int j = 0; j < 6; ++j) sum += cBw[j] * sm.ks[j][b][s];
            sm.y[b][s] += h * sum;
        }
        __syncthreads();  // S5

        if (tid < 16) {  // out[:, t+1, :] for 2 local rows
            int bl = tid >> 3, o = tid & 7;
            int row = (int)rank * 2 + bl;
            float acc = br[o];
            #pragma unroll 8
            for (int s2 = 0; s2 < 64; ++s2) acc += sm.y[row][s2] * Wr[o * 64 + s2];
            out[((b0g + row) * 64 + (t + 1)) * 8 + o] = acc;
        }
    }
}

extern "C" void kernel_launch(void* const* d_in, const int* in_sizes, int n_in,
                              void* d_out, int out_size) {
    const float* ts      = (const float*)d_in[0];
    const float* coeff_d = (const float*)d_in[1];
    const float* coeff_c = (const float*)d_in[2];
    const float* coeff_b = (const float*)d_in[3];
    const float* coeff_a = (const float*)d_in[4];
    const float* Wi1 = (const float*)d_in[5];
    const float* bi1 = (const float*)d_in[6];
    const float* Wi2 = (const float*)d_in[7];
    const float* bi2 = (const float*)d_in[8];
    const float* Wf1 = (const float*)d_in[9];
    const float* bf1 = (const float*)d_in[10];
    const float* Wf2 = (const float*)d_in[11];
    const float* bf2 = (const float*)d_in[12];
    const float* Wf3 = (const float*)d_in[13];
    const float* bf3 = (const float*)d_in[14];
    const float* Wr  = (const float*)d_in[15];
    const float* br  = (const float*)d_in[16];
    float* out = (float*)d_out;

    cudaFuncSetAttribute(cde_kernel, cudaFuncAttributeMaxDynamicSharedMemorySize,
                         (int)sizeof(Smem));

    prep_kernel<<<512, NTHR>>>(Wf3);
    cde_kernel<<<128, NTHR, sizeof(Smem)>>>(ts, coeff_d, coeff_c, coeff_b, coeff_a,
                                            Wi1, bi1, Wi2, bi2, Wf1, bf1, Wf2, bf2,
                                            bf3, Wr, br, out);
}